// round 4
// baseline (speedup 1.0000x reference)
#include <cuda_runtime.h>
#include <cstdint>

// Problem geometry (fixed: GRID = (32,32,32), 6 channels)
#define NCELL 32768          // 32*32*32
#define NCH   6
#define NCTA  128            // <= 148 SMs -> all CTAs co-resident, grid barrier is safe
#define NTHR  256            // 128*256 = 32768 = one thread per cell

// Persistent device state (allocation-free scratch). Re-initialized at the top
// of every launch so the kernel is deterministic across calls/replays.
__device__ __align__(16) float g_phi[2][NCH * NCELL];   // double-buffered phi
__device__ float    g_probe[NCH];                        // nxt values landing on target cell
__device__ unsigned g_bar_arrive;                        // grid barrier arrive counter (0 at rest)
__device__ volatile unsigned g_bar_gen;                  // grid barrier generation (monotonic)

__device__ __forceinline__ void grid_sync_plain()
{
    __syncthreads();
    if (threadIdx.x == 0) {
        __threadfence();                       // release this CTA's writes (cumulative)
        unsigned gen = g_bar_gen;              // MUST read before arriving
        unsigned old = atomicAdd(&g_bar_arrive, 1u);
        if (old == NCTA - 1) {
            atomicExch(&g_bar_arrive, 0u);     // reset for next barrier (others still spinning)
            __threadfence();
            g_bar_gen = gen + 1u;              // release
        } else {
            while (g_bar_gen == gen) { }       // spin (volatile -> L2 load)
        }
        __threadfence();                       // acquire: invalidates L1 (CCTL.IVALL)
    }
    __syncthreads();
}

__global__ void __launch_bounds__(NTHR, 1)
flash_wave_kernel(const float* __restrict__ D,
                  const int* __restrict__ p_sx, const int* __restrict__ p_sy,
                  const int* __restrict__ p_sz, const int* __restrict__ p_ex,
                  const int* __restrict__ p_ey, const int* __restrict__ p_ez,
                  const int* __restrict__ p_mi,
                  float* __restrict__ out)
{
    __shared__ int s_par[7];
    __shared__ int s_reached;

    const int c = blockIdx.x * NTHR + threadIdx.x;   // this thread's cell, 0..32767

    if (threadIdx.x == 0) {
        s_par[0] = *p_sx; s_par[1] = *p_sy; s_par[2] = *p_sz;
        s_par[3] = *p_ex; s_par[4] = *p_ey; s_par[5] = *p_ez;
        s_par[6] = *p_mi;
    }
    __syncthreads();

    const int srcc  = (s_par[0] << 10) + (s_par[1] << 5) + s_par[2];
    const int ct    = (s_par[3] << 10) + (s_par[4] << 5) + s_par[5];
    const int maxit = s_par[6];

    const int x = c >> 10;
    const int y = (c >> 5) & 31;
    const int z = c & 31;

    // Register-resident active_D rows for this cell: D[o][i][cell] + 0.95 (36 regs).
    float Dr[36];
    #pragma unroll
    for (int k = 0; k < 36; k++) Dr[k] = D[k * NCELL + c] + 0.95f;

    // Init phi0: zeros except all 6 channels = 1 at the source cell. Init probe.
    const float v0 = (c == srcc) ? 1.0f : 0.0f;
    #pragma unroll
    for (int i = 0; i < NCH; i++) g_phi[0][i * NCELL + c] = v0;
    if (c == 0) {
        #pragma unroll
        for (int o = 0; o < NCH; o++) g_probe[o] = 0.0f;
    }

    grid_sync_plain();   // publish phi0 + probe init grid-wide

    int p = 0;   // current phi buffer
    int t = 0;   // next history slab index to write

    for (;;) {
        const float* __restrict__ phi = g_phi[p];
        float* __restrict__ nxt       = g_phi[p ^ 1];

        // Read my cell's 6 channels (written by neighbor threads last step).
        float v[6];
        #pragma unroll
        for (int i = 0; i < 6; i++) v[i] = phi[i * NCELL + c];

        // history[t] = phi (pre-update, matching the scan body)
        {
            float* hout = out + (size_t)t * (NCH * NCELL);
            #pragma unroll
            for (int i = 0; i < 6; i++) hout[i * NCELL + c] = v[i];
        }

        t++;
        if (t >= maxit) break;   // last slab written; the final update is discarded anyway

        // phi_out[o] = sum_i Dr[o][i] * v[i], clipped to [0,1]
        float r[6];
        #pragma unroll
        for (int o = 0; o < 6; o++) {
            float a = Dr[o * 6] * v[0];
            #pragma unroll
            for (int i = 1; i < 6; i++) a = fmaf(Dr[o * 6 + i], v[i], a);
            r[o] = fminf(fmaxf(a, 0.0f), 1.0f);
        }

        // Scatter: pn[0,x+1]=r0, pn[1,x-1]=r1, pn[2,y+1]=r2, pn[3,y-1]=r3,
        //          pn[4,z+1]=r4, pn[5,z-1]=r5; boundary planes get explicit zeros.
        // Every nxt location is written exactly once. Writes into the target cell
        // also mirror into g_probe for the reached-check.
        if (x < 31) { int d = c + 1024; nxt[0 * NCELL + d] = r[0]; if (d == ct) g_probe[0] = r[0]; }
        else        { nxt[1 * NCELL + c] = 0.0f; }                    // pn[1, x=31] = 0
        if (x > 0)  { int d = c - 1024; nxt[1 * NCELL + d] = r[1]; if (d == ct) g_probe[1] = r[1]; }
        else        { nxt[0 * NCELL + c] = 0.0f; }                    // pn[0, x=0] = 0
        if (y < 31) { int d = c + 32;   nxt[2 * NCELL + d] = r[2]; if (d == ct) g_probe[2] = r[2]; }
        else        { nxt[3 * NCELL + c] = 0.0f; }                    // pn[3, y=31] = 0
        if (y > 0)  { int d = c - 32;   nxt[3 * NCELL + d] = r[3]; if (d == ct) g_probe[3] = r[3]; }
        else        { nxt[2 * NCELL + c] = 0.0f; }                    // pn[2, y=0] = 0
        if (z < 31) { int d = c + 1;    nxt[4 * NCELL + d] = r[4]; if (d == ct) g_probe[4] = r[4]; }
        else        { nxt[5 * NCELL + c] = 0.0f; }                    // pn[5, z=31] = 0
        if (z > 0)  { int d = c - 1;    nxt[5 * NCELL + d] = r[5]; if (d == ct) g_probe[5] = r[5]; }
        else        { nxt[4 * NCELL + c] = 0.0f; }                    // pn[4, z=0] = 0

        p ^= 1;

        // Grid barrier fused with the reached check (single sync per step).
        __syncthreads();
        if (threadIdx.x == 0) {
            __threadfence();
            unsigned gen = g_bar_gen;
            unsigned old = atomicAdd(&g_bar_arrive, 1u);
            if (old == NCTA - 1) {
                atomicExch(&g_bar_arrive, 0u);
                __threadfence();
                g_bar_gen = gen + 1u;
            } else {
                while (g_bar_gen == gen) { }
            }
            __threadfence();   // acquire -> probe + phi reads below see fresh data
            float s = g_probe[0] + g_probe[1] + g_probe[2]
                    + g_probe[3] + g_probe[4] + g_probe[5];
            s_reached = (s > 0.01f) ? 1 : 0;
        }
        __syncthreads();
        if (s_reached) break;   // uniform across the whole grid: phi frozen from here on
    }

    // Tail fill: history[t..maxit-1] are all the frozen phi (buffer p). Vectorized copy.
    if (t < maxit) {
        const float4* __restrict__ src4 = reinterpret_cast<const float4*>(g_phi[p]);
        float4* __restrict__ out4       = reinterpret_cast<float4*>(out);
        const int NV4 = NCH * NCELL / 4;   // 49152
        for (int idx = c; idx < NV4; idx += NCTA * NTHR) {
            float4 val = src4[idx];
            for (int u = t; u < maxit; u++) {
                out4[(size_t)u * NV4 + idx] = val;
            }
        }
    }
}

extern "C" void kernel_launch(void* const* d_in, const int* in_sizes, int n_in,
                              void* d_out, int out_size)
{
    const float* D  = (const float*)d_in[0];
    const int*   sx = (const int*)d_in[1];
    const int*   sy = (const int*)d_in[2];
    const int*   sz = (const int*)d_in[3];
    const int*   ex = (const int*)d_in[4];
    const int*   ey = (const int*)d_in[5];
    const int*   ez = (const int*)d_in[6];
    const int*   mi = (const int*)d_in[7];

    flash_wave_kernel<<<NCTA, NTHR>>>(D, sx, sy, sz, ex, ey, ez, mi, (float*)d_out);
}